// round 14
// baseline (speedup 1.0000x reference)
#include <cuda_runtime.h>
#include <cuda_fp16.h>
#include <math.h>
#include <stdint.h>

#define BATCH   2
#define SEQ     4096
#define HIDV    2048
#define DSTATE  128
#define KCONV   4
#define DIN     4096
#define HDIM    64
#define NHEAD   64
#define CONVD   (DIN + 2*DSTATE)        /* 4352 */
#define PROJ    (2*(DIN+DSTATE)+NHEAD)  /* 8512 */
#define MTOK    (BATCH*SEQ)             /* 8192 */
#define TILE    32

// ---------------- scratch (no allocations allowed) ----------------
__device__ float g_zx  [(size_t)MTOK*PROJ];    // in_proj output (fp32)
__device__ float g_conv[(size_t)MTOK*CONVD];   // conv+silu output
__device__ float g_dt  [MTOK*NHEAD];           // softplus(dt+bias)
__device__ float g_y   [(size_t)MTOK*DIN];     // SSD output (pre-norm)

// fp16 planes for tensor-core GEMMs: A single, B hi+lo
__device__ __half g_hs_h[(size_t)MTOK*HIDV];
__device__ __half g_w1_h[(size_t)PROJ*HIDV], g_w1_l[(size_t)PROJ*HIDV];
__device__ __half g_w2_h[(size_t)HIDV*DIN],  g_w2_l[(size_t)HIDV*DIN];
__device__ __half g_yn_h[(size_t)MTOK*DIN];

// ---------------- helpers ----------------
__device__ __forceinline__ uint32_t smem_u32(const void* p) {
    uint32_t a;
    asm("{ .reg .u64 t; cvta.to.shared.u64 t, %1; cvt.u32.u64 %0, t; }" : "=r"(a) : "l"(p));
    return a;
}
__device__ __forceinline__ void cp_async16(uint32_t dst, const void* src, int srcsize) {
    asm volatile("cp.async.ca.shared.global [%0], [%1], 16, %2;"
                 :: "r"(dst), "l"(src), "r"(srcsize) : "memory");
}
#define CP_COMMIT() asm volatile("cp.async.commit_group;" ::: "memory")
#define CP_WAIT0()  asm volatile("cp.async.wait_group 0;" ::: "memory")
#define CP_WAIT1()  asm volatile("cp.async.wait_group 1;" ::: "memory")

__device__ __forceinline__ void ldmx4(uint32_t* r, uint32_t addr) {
    asm volatile("ldmatrix.sync.aligned.m8n8.x4.shared.b16 {%0,%1,%2,%3}, [%4];"
                 : "=r"(r[0]), "=r"(r[1]), "=r"(r[2]), "=r"(r[3]) : "r"(addr));
}
__device__ __forceinline__ void mma16816h(float* d, const uint32_t* a, const uint32_t* b) {
    asm volatile(
        "mma.sync.aligned.m16n8k16.row.col.f32.f16.f16.f32 "
        "{%0,%1,%2,%3}, {%4,%5,%6,%7}, {%8,%9}, {%0,%1,%2,%3};"
        : "+f"(d[0]), "+f"(d[1]), "+f"(d[2]), "+f"(d[3])
        : "r"(a[0]), "r"(a[1]), "r"(a[2]), "r"(a[3]), "r"(b[0]), "r"(b[1]));
}

// ---------------- fp32 -> fp16 converts ----------------
// dst_sel 0: hs -> single A plane. 1: w1 -> hi/lo. 2: w2 -> hi/lo.
__global__ void convert_kernel(const float* __restrict__ src, int dst_sel, size_t n4)
{
    size_t i = (size_t)blockIdx.x*256 + threadIdx.x;
    if (i >= n4) return;
    float4 v = reinterpret_cast<const float4*>(src)[i];
    __half h0=__float2half_rn(v.x), h1=__float2half_rn(v.y),
           h2=__float2half_rn(v.z), h3=__float2half_rn(v.w);
    if (dst_sel == 0) {
        reinterpret_cast<__half2*>(g_hs_h)[i*2]   = __halves2half2(h0, h1);
        reinterpret_cast<__half2*>(g_hs_h)[i*2+1] = __halves2half2(h2, h3);
        return;
    }
    __half *hi = (dst_sel == 1) ? g_w1_h : g_w2_h;
    __half *lo = (dst_sel == 1) ? g_w1_l : g_w2_l;
    reinterpret_cast<__half2*>(hi)[i*2]   = __halves2half2(h0, h1);
    reinterpret_cast<__half2*>(hi)[i*2+1] = __halves2half2(h2, h3);
    reinterpret_cast<__half2*>(lo)[i*2]   = __halves2half2(
        __float2half_rn(v.x-__half2float(h0)), __float2half_rn(v.y-__half2float(h1)));
    reinterpret_cast<__half2*>(lo)[i*2+1] = __halves2half2(
        __float2half_rn(v.z-__half2float(h2)), __float2half_rn(v.w-__half2float(h3)));
}

// ============ tensor-core GEMM: C[M,N] = A[M,K]*B[N,K]^T, fp16 2-pass ============
// 3765us anchor — DO NOT TOUCH.
#define BK      32
#define SAK_B   80
#define PLANE_B (128*SAK_B)
#define BUF_B   (3*PLANE_B)
#define SMT     (2*BUF_B)

__global__ void __launch_bounds__(256) gemm_mma(int which, float* Cout, int M, int N, int Kd)
{
    extern __shared__ char sm[];
    const __half *Ap, *Bh, *Bl;
    float* Cp;
    if (which == 0) { Ap=g_hs_h; Bh=g_w1_h; Bl=g_w1_l; Cp=g_zx; }
    else            { Ap=g_yn_h; Bh=g_w2_h; Bl=g_w2_l; Cp=Cout; }

    const uint32_t sb = smem_u32(sm);
    const int tid  = threadIdx.x;
    const int lane = tid & 31, wid = tid >> 5;
    const int wm = wid & 1, wn = wid >> 1;
    const int lr = lane >> 2, lc = lane & 3;
    const int m0 = blockIdx.y * 128, n0 = blockIdx.x * 128;
    const int nk = Kd / BK;

    auto stage = [&](int kc, int buf) {
        const int k0 = kc * BK;
        const uint32_t base = sb + buf * BUF_B;
#pragma unroll
        for (int it = 0; it < 2; it++) {
            int idx = it*256 + tid;
            int row = idx >> 2, ch = idx & 3;
            const __half* s = Ap + (size_t)(m0 + row)*Kd + k0 + ch*8;
            cp_async16(base + row*SAK_B + ch*16, s, 16);
        }
#pragma unroll
        for (int it = 0; it < 4; it++) {
            int idx = it*256 + tid;
            int pl  = idx >> 9;
            int row = (idx >> 2) & 127, ch = idx & 3;
            int gn = n0 + row;
            const __half* s = (pl ? Bl : Bh) + (size_t)gn*Kd + k0 + ch*8;
            cp_async16(base + (1+pl)*PLANE_B + row*SAK_B + ch*16, s, gn < N ? 16 : 0);
        }
    };

    float d[4][4][4];
#pragma unroll
    for (int mi = 0; mi < 4; mi++)
#pragma unroll
        for (int ni = 0; ni < 4; ni++)
#pragma unroll
            for (int r = 0; r < 4; r++) d[mi][ni][r] = 0.f;

    stage(0, 0); CP_COMMIT();

    for (int k = 0; k < nk; k++) {
        const int buf = k & 1;
        if (k + 1 < nk) { stage(k + 1, buf ^ 1); CP_COMMIT(); CP_WAIT1(); }
        else            { CP_WAIT0(); }
        __syncthreads();

        const uint32_t base = sb + buf * BUF_B;
        const int arow = wm*64 + (lane & 15);
        const int akof = (lane & 16) ? 16 : 0;
        const int bkof = (lane & 8)  ? 16 : 0;
#pragma unroll
        for (int ks = 0; ks < BK; ks += 16) {
            uint32_t ah[4][4], bh[2][4], bl[2][4];
#pragma unroll
            for (int mi = 0; mi < 4; mi++) {
                uint32_t ao = (uint32_t)((arow + mi*16)*SAK_B + ks*2 + akof);
                ldmx4(ah[mi], base + ao);
            }
#pragma unroll
            for (int pr = 0; pr < 2; pr++) {
                int brow = wn*32 + pr*16 + (lane & 7) + ((lane & 16) ? 8 : 0);
                uint32_t bo = (uint32_t)(brow*SAK_B + ks*2 + bkof);
                ldmx4(bh[pr], base + PLANE_B   + bo);
                ldmx4(bl[pr], base + 2*PLANE_B + bo);
            }
#pragma unroll
            for (int mi = 0; mi < 4; mi++)
#pragma unroll
                for (int ni = 0; ni < 4; ni++) {
                    const uint32_t* bhp = &bh[ni>>1][(ni&1)*2];
                    const uint32_t* blp = &bl[ni>>1][(ni&1)*2];
                    mma16816h(d[mi][ni], ah[mi], bhp);
                    mma16816h(d[mi][ni], ah[mi], blp);
                }
        }
        __syncthreads();
    }

#pragma unroll
    for (int mi = 0; mi < 4; mi++) {
        int m = m0 + wm*64 + mi*16 + lr;
#pragma unroll
        for (int ni = 0; ni < 4; ni++) {
            int n = n0 + wn*32 + ni*8 + lc*2;
            if (n < N) {
                *reinterpret_cast<float2*>(Cp + (size_t)m*N + n) =
                    make_float2(d[mi][ni][0], d[mi][ni][1]);
                *reinterpret_cast<float2*>(Cp + (size_t)(m+8)*N + n) =
                    make_float2(d[mi][ni][2], d[mi][ni][3]);
            }
        }
    }
}

// ---------------- causal conv1d (K=4) + bias + silu, 32-token smem tile ----------------
#define CMT 32
__global__ void __launch_bounds__(256) conv_kernel(const float* __restrict__ w,
                                                   const float* __restrict__ bias)
{
    __shared__ float s[CMT + 3][256];
    const int tid = threadIdx.x;
    const int m0  = blockIdx.x * CMT;
    const int ch  = blockIdx.y * 256 + tid;

#pragma unroll
    for (int i = 0; i < CMT + 3; i++) {
        int gm = m0 - 3 + i;
        if (gm < 0) gm = 0;
        s[i][tid] = g_zx[(size_t)gm*PROJ + DIN + ch];
    }
    __syncthreads();

    const float w0 = w[ch*KCONV+0], w1 = w[ch*KCONV+1],
                w2 = w[ch*KCONV+2], w3 = w[ch*KCONV+3];
    const float b = bias[ch];
#pragma unroll
    for (int i = 0; i < CMT; i++) {
        int m = m0 + i;
        int t = m & (SEQ-1);
        float acc = b;
        if (t >= 3) acc += s[i  ][tid] * w0;
        if (t >= 2) acc += s[i+1][tid] * w1;
        if (t >= 1) acc += s[i+2][tid] * w2;
        acc += s[i+3][tid] * w3;
        acc = acc / (1.f + expf(-acc));
        g_conv[(size_t)m*CONVD + ch] = acc;
    }
}

// ---------------- dt = softplus(dt_raw + dt_bias) ----------------
__global__ void dt_kernel(const float* __restrict__ dtb)
{
    int id = blockIdx.x*256 + threadIdx.x;          // m*64+h
    int m = id >> 6, h = id & 63;
    float v = g_zx[(size_t)m*PROJ + DIN + CONVD + h] + dtb[h];
    g_dt[id] = (v > 20.f) ? v : log1pf(expf(v));
}

// ---------------- SSD recurrence: p-split, float4 conflict-free loads ----------------
// grid (NHEAD, BATCH*2); block 512. ph = blockIdx.y&1 selects p half.
// p_loc = tid>>4 (0..31), p = ph*32+p_loc; q = tid&15.
// Thread owns n = j*64 + q*4 + {0..3}, j=0..1 (8 n-values, 2 float4 groups).
// For fixed j, the 16 q-chunks are contiguous 256B -> conflict-free LDS.128
// (2-way p-broadcast). 4 LDS per token vs 16 in the old layout.
__global__ void __launch_bounds__(512) ssd_kernel(const float* __restrict__ A_log,
                                                  const float* __restrict__ Dv)
{
    const int h  = blockIdx.x;
    const int b  = blockIdx.y >> 1;
    const int ph = blockIdx.y & 1;
    const int tid = threadIdx.x;
    const int p_loc = tid >> 4, q = tid & 15;
    const int p = ph*32 + p_loc;

    __shared__ float sB[TILE][DSTATE];
    __shared__ float sC[TILE][DSTATE];
    __shared__ float sX[TILE][32];
    __shared__ float s_dt[TILE], s_eadt[TILE];

    const float A  = -expf(A_log[h]);
    const float Dh = Dv[h];

    float H[8];
#pragma unroll
    for (int j = 0; j < 8; j++) H[j] = 0.f;

    for (int t0 = 0; t0 < SEQ; t0 += TILE) {
        const size_t mbase = (size_t)b*SEQ + t0;
        // stage B, C (2048 float4 over 512 threads)
#pragma unroll
        for (int it = 0; it < 4; it++) {
            int idx = it*512 + tid;
            int r = idx >> 6, c = idx & 63;
            const float* rowp = g_conv + (mbase + r)*CONVD + DIN;
            if (c < 32) *(float4*)&sB[r][c*4]      = *(const float4*)(rowp + c*4);
            else        *(float4*)&sC[r][(c-32)*4] = *(const float4*)(rowp + DSTATE + (c-32)*4);
        }
        // stage x slice for this p-half (32 rows x 32 cols = 256 float4)
        if (tid < 256) {
            int r = tid >> 3, c = tid & 7;
            *(float4*)&sX[r][c*4] =
                *(const float4*)(g_conv + (mbase + r)*CONVD + h*HDIM + ph*32 + c*4);
        }
        if (tid < TILE) {
            float dtv = g_dt[(mbase + tid)*NHEAD + h];
            s_dt[tid]   = dtv;
            s_eadt[tid] = expf(A * dtv);
        }
        __syncthreads();

        for (int ll = 0; ll < TILE; ll++) {
            float e  = s_eadt[ll];
            float xv = sX[ll][p_loc];
            float f  = s_dt[ll] * xv;
            float part = 0.f;
#pragma unroll
            for (int j = 0; j < 2; j++) {
                int col = j*64 + q*4;
                float4 bb = *(const float4*)&sB[ll][col];
                float4 cc = *(const float4*)&sC[ll][col];
                H[4*j+0] = e*H[4*j+0] + f*bb.x;
                H[4*j+1] = e*H[4*j+1] + f*bb.y;
                H[4*j+2] = e*H[4*j+2] + f*bb.z;
                H[4*j+3] = e*H[4*j+3] + f*bb.w;
                part += cc.x*H[4*j+0] + cc.y*H[4*j+1]
                      + cc.z*H[4*j+2] + cc.w*H[4*j+3];
            }
            part += __shfl_down_sync(0xffffffffu, part, 8, 16);
            part += __shfl_down_sync(0xffffffffu, part, 4, 16);
            part += __shfl_down_sync(0xffffffffu, part, 2, 16);
            part += __shfl_down_sync(0xffffffffu, part, 1, 16);
            if (q == 0)
                g_y[(mbase + ll)*DIN + h*HDIM + p] = part + Dh * xv;
        }
        __syncthreads();
    }
}

// ---------------- gated RMSNorm -> single fp16 plane ----------------
__global__ void __launch_bounds__(256) rmsnorm_kernel(const float* __restrict__ w)
{
    int m = blockIdx.x;
    int tid = threadIdx.x;
    float prod[16];
    float ss = 0.f;
#pragma unroll
    for (int i = 0; i < 16; i++) {
        int col = i*256 + tid;
        float y = g_y[(size_t)m*DIN + col];
        float z = g_zx[(size_t)m*PROJ + col];
        float p = y * (z / (1.f + expf(-z)));
        prod[i] = p;
        ss += p*p;
    }
    __shared__ float red[256];
    red[tid] = ss;
    __syncthreads();
    for (int off = 128; off; off >>= 1) {
        if (tid < off) red[tid] += red[tid + off];
        __syncthreads();
    }
    float scale = rsqrtf(red[0] / (float)DIN + 1e-5f);
#pragma unroll
    for (int i = 0; i < 16; i++) {
        int col = i*256 + tid;
        g_yn_h[(size_t)m*DIN + col] = __float2half_rn(prod[i] * scale * w[col]);
    }
}

// ---------------- launch ----------------
extern "C" void kernel_launch(void* const* d_in, const int* in_sizes, int n_in,
                              void* d_out, int out_size)
{
    const float* hs   = (const float*)d_in[0];
    const float* w1   = (const float*)d_in[1];
    const float* cw   = (const float*)d_in[2];
    const float* cb   = (const float*)d_in[3];
    const float* dtb  = (const float*)d_in[4];
    const float* alog = (const float*)d_in[5];
    const float* Dv   = (const float*)d_in[6];
    const float* nw   = (const float*)d_in[7];
    const float* w2   = (const float*)d_in[8];
    float* out = (float*)d_out;

    static int smem_set = 0;
    if (!smem_set) {
        cudaFuncSetAttribute(gemm_mma, cudaFuncAttributeMaxDynamicSharedMemorySize, SMT);
        smem_set = 1;
    }

    // 0. pre-convert GEMM inputs to fp16 planes
    convert_kernel<<<(MTOK*(size_t)HIDV/4 + 255)/256, 256>>>(hs, 0, MTOK*(size_t)HIDV/4);
    convert_kernel<<<(PROJ*(size_t)HIDV/4 + 255)/256, 256>>>(w1, 1, PROJ*(size_t)HIDV/4);
    convert_kernel<<<(HIDV*(size_t)DIN/4 + 255)/256, 256>>>(w2, 2, HIDV*(size_t)DIN/4);

    // 1. in_proj GEMM: g_zx[8192,8512] = hs @ w1^T
    gemm_mma<<<dim3((PROJ+127)/128, MTOK/128), 256, SMT>>>(0, nullptr, MTOK, PROJ, HIDV);
    // 2. conv + silu (tiled)
    conv_kernel<<<dim3(MTOK/CMT, CONVD/256), 256>>>(cw, cb);
    // 3. dt softplus
    dt_kernel<<<(MTOK*NHEAD)/256, 256>>>(dtb);
    // 4. SSD recurrence (p-split, float4 loads)
    ssd_kernel<<<dim3(NHEAD, BATCH*2), 512>>>(alog, Dv);
    // 5. gated rmsnorm -> fp16
    rmsnorm_kernel<<<MTOK, 256>>>(nw);
    // 6. out_proj GEMM: out[8192,2048] = yn @ w2^T
    gemm_mma<<<dim3(HIDV/128, MTOK/128), 256, SMT>>>(1, out, MTOK, HIDV, DIN);
}

// round 15
// speedup vs baseline: 1.0368x; 1.0368x over previous
#include <cuda_runtime.h>
#include <cuda_fp16.h>
#include <math.h>
#include <stdint.h>

#define BATCH   2
#define SEQ     4096
#define HIDV    2048
#define DSTATE  128
#define KCONV   4
#define DIN     4096
#define HDIM    64
#define NHEAD   64
#define CONVD   (DIN + 2*DSTATE)        /* 4352 */
#define PROJ    (2*(DIN+DSTATE)+NHEAD)  /* 8512 */
#define MTOK    (BATCH*SEQ)             /* 8192 */
#define TILE    32

// ---------------- scratch (no allocations allowed) ----------------
__device__ float g_zx  [(size_t)MTOK*PROJ];    // in_proj output (fp32)
__device__ float g_conv[(size_t)MTOK*CONVD];   // conv+silu output
__device__ float g_dt  [MTOK*NHEAD];           // softplus(dt+bias)
__device__ float g_y   [(size_t)MTOK*DIN];     // SSD output (pre-norm)

// fp16 planes for tensor-core GEMMs: A single, B hi+lo
__device__ __half g_hs_h[(size_t)MTOK*HIDV];
__device__ __half g_w1_h[(size_t)PROJ*HIDV], g_w1_l[(size_t)PROJ*HIDV];
__device__ __half g_w2_h[(size_t)HIDV*DIN],  g_w2_l[(size_t)HIDV*DIN];
__device__ __half g_yn_h[(size_t)MTOK*DIN];

// ---------------- helpers ----------------
__device__ __forceinline__ uint32_t smem_u32(const void* p) {
    uint32_t a;
    asm("{ .reg .u64 t; cvta.to.shared.u64 t, %1; cvt.u32.u64 %0, t; }" : "=r"(a) : "l"(p));
    return a;
}
__device__ __forceinline__ void cp_async16(uint32_t dst, const void* src, int srcsize) {
    asm volatile("cp.async.ca.shared.global [%0], [%1], 16, %2;"
                 :: "r"(dst), "l"(src), "r"(srcsize) : "memory");
}
#define CP_COMMIT() asm volatile("cp.async.commit_group;" ::: "memory")
#define CP_WAIT0()  asm volatile("cp.async.wait_group 0;" ::: "memory")
#define CP_WAIT1()  asm volatile("cp.async.wait_group 1;" ::: "memory")

__device__ __forceinline__ void ldmx4(uint32_t* r, uint32_t addr) {
    asm volatile("ldmatrix.sync.aligned.m8n8.x4.shared.b16 {%0,%1,%2,%3}, [%4];"
                 : "=r"(r[0]), "=r"(r[1]), "=r"(r[2]), "=r"(r[3]) : "r"(addr));
}
__device__ __forceinline__ void mma16816h(float* d, const uint32_t* a, const uint32_t* b) {
    asm volatile(
        "mma.sync.aligned.m16n8k16.row.col.f32.f16.f16.f32 "
        "{%0,%1,%2,%3}, {%4,%5,%6,%7}, {%8,%9}, {%0,%1,%2,%3};"
        : "+f"(d[0]), "+f"(d[1]), "+f"(d[2]), "+f"(d[3])
        : "r"(a[0]), "r"(a[1]), "r"(a[2]), "r"(a[3]), "r"(b[0]), "r"(b[1]));
}

// ---------------- fp32 -> fp16 converts ----------------
// dst_sel 0: hs -> single A plane. 1: w1 -> hi/lo. 2: w2 -> hi/lo.
__global__ void convert_kernel(const float* __restrict__ src, int dst_sel, size_t n4)
{
    size_t i = (size_t)blockIdx.x*256 + threadIdx.x;
    if (i >= n4) return;
    float4 v = reinterpret_cast<const float4*>(src)[i];
    __half h0=__float2half_rn(v.x), h1=__float2half_rn(v.y),
           h2=__float2half_rn(v.z), h3=__float2half_rn(v.w);
    if (dst_sel == 0) {
        reinterpret_cast<__half2*>(g_hs_h)[i*2]   = __halves2half2(h0, h1);
        reinterpret_cast<__half2*>(g_hs_h)[i*2+1] = __halves2half2(h2, h3);
        return;
    }
    __half *hi = (dst_sel == 1) ? g_w1_h : g_w2_h;
    __half *lo = (dst_sel == 1) ? g_w1_l : g_w2_l;
    reinterpret_cast<__half2*>(hi)[i*2]   = __halves2half2(h0, h1);
    reinterpret_cast<__half2*>(hi)[i*2+1] = __halves2half2(h2, h3);
    reinterpret_cast<__half2*>(lo)[i*2]   = __halves2half2(
        __float2half_rn(v.x-__half2float(h0)), __float2half_rn(v.y-__half2float(h1)));
    reinterpret_cast<__half2*>(lo)[i*2+1] = __halves2half2(
        __float2half_rn(v.z-__half2float(h2)), __float2half_rn(v.w-__half2float(h3)));
}

// ============ tensor-core GEMM: C[M,N] = A[M,K]*B[N,K]^T, fp16 2-pass ============
// Same skeleton as the 3765us anchor (2 buffers, 2 barriers, affine addressing),
// but BK=64 to halve per-chunk overhead. Rows are 144B = 128B data + 16B pad;
// 16B-chunk phase = (9*row + c) mod 32 -> conflict-free per 8-lane ldmatrix group.
#define BK      64
#define SAK_B   144
#define PLANE_B (128*SAK_B)             /* 18432 B per plane            */
#define BUF_B   (3*PLANE_B)             /* A Bhi Blo = 55296 B          */
#define SMT     (2*BUF_B)               /* 110592 B -> 2 CTAs/SM        */

__global__ void __launch_bounds__(256) gemm_mma(int which, float* Cout, int M, int N, int Kd)
{
    extern __shared__ char sm[];
    const __half *Ap, *Bh, *Bl;
    float* Cp;
    if (which == 0) { Ap=g_hs_h; Bh=g_w1_h; Bl=g_w1_l; Cp=g_zx; }
    else            { Ap=g_yn_h; Bh=g_w2_h; Bl=g_w2_l; Cp=Cout; }

    const uint32_t sb = smem_u32(sm);
    const int tid  = threadIdx.x;
    const int lane = tid & 31, wid = tid >> 5;
    const int wm = wid & 1, wn = wid >> 1;          // 2 x 4 warp grid
    const int lr = lane >> 2, lc = lane & 3;
    const int m0 = blockIdx.y * 128, n0 = blockIdx.x * 128;
    const int nk = Kd / BK;

    // staging: 12 cp.async per thread (A: 4 iters, B: 8 iters)
    auto stage = [&](int kc, int buf) {
        const int k0 = kc * BK;
        const uint32_t base = sb + buf * BUF_B;
#pragma unroll
        for (int it = 0; it < 4; it++) {
            int idx = it*256 + tid;                  // 0..1023
            int row = idx >> 3, c = idx & 7;
            const __half* s = Ap + (size_t)(m0 + row)*Kd + k0 + c*8;
            cp_async16(base + row*SAK_B + c*16, s, 16);
        }
#pragma unroll
        for (int it = 0; it < 8; it++) {
            int idx = it*256 + tid;                  // 0..2047
            int pl  = idx >> 10;                     // 0=hi 1=lo
            int row = (idx >> 3) & 127, c = idx & 7;
            int gn = n0 + row;
            const __half* s = (pl ? Bl : Bh) + (size_t)gn*Kd + k0 + c*8;
            cp_async16(base + (1+pl)*PLANE_B + row*SAK_B + c*16, s, gn < N ? 16 : 0);
        }
    };

    float d[4][4][4];
#pragma unroll
    for (int mi = 0; mi < 4; mi++)
#pragma unroll
        for (int ni = 0; ni < 4; ni++)
#pragma unroll
            for (int r = 0; r < 4; r++) d[mi][ni][r] = 0.f;

    stage(0, 0); CP_COMMIT();

    for (int k = 0; k < nk; k++) {
        const int buf = k & 1;
        if (k + 1 < nk) { stage(k + 1, buf ^ 1); CP_COMMIT(); CP_WAIT1(); }
        else            { CP_WAIT0(); }
        __syncthreads();

        const uint32_t base = sb + buf * BUF_B;
        const int arow = wm*64 + (lane & 15);
        const int akof = (lane & 16) ? 16 : 0;       // bytes (8 fp16)
        const int bkof = (lane & 8)  ? 16 : 0;
#pragma unroll
        for (int ks = 0; ks < BK; ks += 16) {
            uint32_t ah[4][4], bh[2][4], bl[2][4];
#pragma unroll
            for (int mi = 0; mi < 4; mi++) {
                uint32_t ao = (uint32_t)((arow + mi*16)*SAK_B + ks*2 + akof);
                ldmx4(ah[mi], base + ao);
            }
#pragma unroll
            for (int pr = 0; pr < 2; pr++) {
                int brow = wn*32 + pr*16 + (lane & 7) + ((lane & 16) ? 8 : 0);
                uint32_t bo = (uint32_t)(brow*SAK_B + ks*2 + bkof);
                ldmx4(bh[pr], base + PLANE_B   + bo);
                ldmx4(bl[pr], base + 2*PLANE_B + bo);
            }
#pragma unroll
            for (int mi = 0; mi < 4; mi++)
#pragma unroll
                for (int ni = 0; ni < 4; ni++) {
                    const uint32_t* bhp = &bh[ni>>1][(ni&1)*2];
                    const uint32_t* blp = &bl[ni>>1][(ni&1)*2];
                    mma16816h(d[mi][ni], ah[mi], bhp);
                    mma16816h(d[mi][ni], ah[mi], blp);
                }
        }
        __syncthreads();
    }

    // epilogue
#pragma unroll
    for (int mi = 0; mi < 4; mi++) {
        int m = m0 + wm*64 + mi*16 + lr;
#pragma unroll
        for (int ni = 0; ni < 4; ni++) {
            int n = n0 + wn*32 + ni*8 + lc*2;
            if (n < N) {
                *reinterpret_cast<float2*>(Cp + (size_t)m*N + n) =
                    make_float2(d[mi][ni][0], d[mi][ni][1]);
                *reinterpret_cast<float2*>(Cp + (size_t)(m+8)*N + n) =
                    make_float2(d[mi][ni][2], d[mi][ni][3]);
            }
        }
    }
}

// ---------------- causal conv1d (K=4) + bias + silu, 32-token smem tile ----------------
#define CMT 32
__global__ void __launch_bounds__(256) conv_kernel(const float* __restrict__ w,
                                                   const float* __restrict__ bias)
{
    __shared__ float s[CMT + 3][256];
    const int tid = threadIdx.x;
    const int m0  = blockIdx.x * CMT;
    const int ch  = blockIdx.y * 256 + tid;

#pragma unroll
    for (int i = 0; i < CMT + 3; i++) {
        int gm = m0 - 3 + i;
        if (gm < 0) gm = 0;
        s[i][tid] = g_zx[(size_t)gm*PROJ + DIN + ch];
    }
    __syncthreads();

    const float w0 = w[ch*KCONV+0], w1 = w[ch*KCONV+1],
                w2 = w[ch*KCONV+2], w3 = w[ch*KCONV+3];
    const float b = bias[ch];
#pragma unroll
    for (int i = 0; i < CMT; i++) {
        int m = m0 + i;
        int t = m & (SEQ-1);
        float acc = b;
        if (t >= 3) acc += s[i  ][tid] * w0;
        if (t >= 2) acc += s[i+1][tid] * w1;
        if (t >= 1) acc += s[i+2][tid] * w2;
        acc += s[i+3][tid] * w3;
        acc = acc / (1.f + expf(-acc));
        g_conv[(size_t)m*CONVD + ch] = acc;
    }
}

// ---------------- dt = softplus(dt_raw + dt_bias) ----------------
__global__ void dt_kernel(const float* __restrict__ dtb)
{
    int id = blockIdx.x*256 + threadIdx.x;          // m*64+h
    int m = id >> 6, h = id & 63;
    float v = g_zx[(size_t)m*PROJ + DIN + CONVD + h] + dtb[h];
    g_dt[id] = (v > 20.f) ? v : log1pf(expf(v));
}

// ---------------- SSD as the exact sequential recurrence (R13 anchor) ----------------
__global__ void __launch_bounds__(512) ssd_kernel(const float* __restrict__ A_log,
                                                  const float* __restrict__ Dv)
{
    const int h = blockIdx.x;
    const int b = blockIdx.y;
    const int tid = threadIdx.x;
    const int p = tid >> 3, q = tid & 7;

    __shared__ float sB[TILE][DSTATE];
    __shared__ float sC[TILE][DSTATE];
    __shared__ float sX[TILE][HDIM];
    __shared__ float s_dt[TILE], s_eadt[TILE];

    const float A  = -expf(A_log[h]);
    const float Dh = Dv[h];

    float H[16];
#pragma unroll
    for (int j = 0; j < 16; j++) H[j] = 0.f;

    for (int t0 = 0; t0 < SEQ; t0 += TILE) {
        const size_t mbase = (size_t)b*SEQ + t0;
#pragma unroll
        for (int it = 0; it < 4; it++) {
            int idx = it*512 + tid;
            int r = idx >> 6, c = idx & 63;
            const float* rowp = g_conv + (mbase + r)*CONVD + DIN;
            if (c < 32) *(float4*)&sB[r][c*4]      = *(const float4*)(rowp + c*4);
            else        *(float4*)&sC[r][(c-32)*4] = *(const float4*)(rowp + DSTATE + (c-32)*4);
        }
        {
            int r = tid >> 4, c = tid & 15;
            *(float4*)&sX[r][c*4] =
                *(const float4*)(g_conv + (mbase + r)*CONVD + h*HDIM + c*4);
        }
        if (tid < TILE) {
            float dtv = g_dt[(mbase + tid)*NHEAD + h];
            s_dt[tid]   = dtv;
            s_eadt[tid] = expf(A * dtv);
        }
        __syncthreads();

        for (int ll = 0; ll < TILE; ll++) {
            float e = s_eadt[ll];
            float f = s_dt[ll] * sX[ll][p];
            float part = 0.f;
#pragma unroll
            for (int j = 0; j < 8; j++) {
                int col = j*16 + q*2;
                float2 bb = *(const float2*)&sB[ll][col];
                float2 cc = *(const float2*)&sC[ll][col];
                H[2*j]   = e*H[2*j]   + f*bb.x;
                H[2*j+1] = e*H[2*j+1] + f*bb.y;
                part += cc.x*H[2*j] + cc.y*H[2*j+1];
            }
            part += __shfl_down_sync(0xffffffffu, part, 4, 8);
            part += __shfl_down_sync(0xffffffffu, part, 2, 8);
            part += __shfl_down_sync(0xffffffffu, part, 1, 8);
            if (q == 0)
                g_y[(mbase + ll)*DIN + h*HDIM + p] = part + Dh * sX[ll][p];
        }
        __syncthreads();
    }
}

// ---------------- gated RMSNorm -> single fp16 plane ----------------
__global__ void __launch_bounds__(256) rmsnorm_kernel(const float* __restrict__ w)
{
    int m = blockIdx.x;
    int tid = threadIdx.x;
    float prod[16];
    float ss = 0.f;
#pragma unroll
    for (int i = 0; i < 16; i++) {
        int col = i*256 + tid;
        float y = g_y[(size_t)m*DIN + col];
        float z = g_zx[(size_t)m*PROJ + col];
        float p = y * (z / (1.f + expf(-z)));
        prod[i] = p;
        ss += p*p;
    }
    __shared__ float red[256];
    red[tid] = ss;
    __syncthreads();
    for (int off = 128; off; off >>= 1) {
        if (tid < off) red[tid] += red[tid + off];
        __syncthreads();
    }
    float scale = rsqrtf(red[0] / (float)DIN + 1e-5f);
#pragma unroll
    for (int i = 0; i < 16; i++) {
        int col = i*256 + tid;
        g_yn_h[(size_t)m*DIN + col] = __float2half_rn(prod[i] * scale * w[col]);
    }
}

// ---------------- launch ----------------
extern "C" void kernel_launch(void* const* d_in, const int* in_sizes, int n_in,
                              void* d_out, int out_size)
{
    const float* hs   = (const float*)d_in[0];
    const float* w1   = (const float*)d_in[1];
    const float* cw   = (const float*)d_in[2];
    const float* cb   = (const float*)d_in[3];
    const float* dtb  = (const float*)d_in[4];
    const float* alog = (const float*)d_in[5];
    const float* Dv   = (const float*)d_in[6];
    const float* nw   = (const float*)d_in[7];
    const float* w2   = (const float*)d_in[8];
    float* out = (float*)d_out;

    static int smem_set = 0;
    if (!smem_set) {
        cudaFuncSetAttribute(gemm_mma, cudaFuncAttributeMaxDynamicSharedMemorySize, SMT);
        smem_set = 1;
    }

    // 0. pre-convert GEMM inputs to fp16 planes
    convert_kernel<<<(MTOK*(size_t)HIDV/4 + 255)/256, 256>>>(hs, 0, MTOK*(size_t)HIDV/4);
    convert_kernel<<<(PROJ*(size_t)HIDV/4 + 255)/256, 256>>>(w1, 1, PROJ*(size_t)HIDV/4);
    convert_kernel<<<(HIDV*(size_t)DIN/4 + 255)/256, 256>>>(w2, 2, HIDV*(size_t)DIN/4);

    // 1. in_proj GEMM: g_zx[8192,8512] = hs @ w1^T
    gemm_mma<<<dim3((PROJ+127)/128, MTOK/128), 256, SMT>>>(0, nullptr, MTOK, PROJ, HIDV);
    // 2. conv + silu (tiled)
    conv_kernel<<<dim3(MTOK/CMT, CONVD/256), 256>>>(cw, cb);
    // 3. dt softplus
    dt_kernel<<<(MTOK*NHEAD)/256, 256>>>(dtb);
    // 4. SSD recurrence
    ssd_kernel<<<dim3(NHEAD, BATCH), 512>>>(alog, Dv);
    // 5. gated rmsnorm -> fp16
    rmsnorm_kernel<<<MTOK, 256>>>(nw);
    // 6. out_proj GEMM: out[8192,2048] = yn @ w2^T
    gemm_mma<<<dim3(HIDV/128, MTOK/128), 256, SMT>>>(1, out, MTOK, HIDV, DIN);
}

// round 16
// speedup vs baseline: 1.2929x; 1.2470x over previous
#include <cuda_runtime.h>
#include <cuda_fp16.h>
#include <math.h>
#include <stdint.h>

#define BATCH   2
#define SEQ     4096
#define HIDV    2048
#define DSTATE  128
#define KCONV   4
#define DIN     4096
#define HDIM    64
#define NHEAD   64
#define CONVD   (DIN + 2*DSTATE)        /* 4352 */
#define PROJ    (2*(DIN+DSTATE)+NHEAD)  /* 8512 */
#define MTOK    (BATCH*SEQ)             /* 8192 */
#define TILE    32

// ---------------- scratch (no allocations allowed) ----------------
__device__ float g_zx  [(size_t)MTOK*PROJ];    // in_proj output (fp32)
__device__ float g_conv[(size_t)MTOK*CONVD];   // conv+silu output
__device__ float g_dt  [MTOK*NHEAD];           // softplus(dt+bias)
__device__ float g_y   [(size_t)MTOK*DIN];     // SSD output (pre-norm)

// fp16 planes for tensor-core GEMMs (single plane per operand)
__device__ __half g_hs_h[(size_t)MTOK*HIDV];
__device__ __half g_w1_h[(size_t)PROJ*HIDV];
__device__ __half g_w2_h[(size_t)HIDV*DIN];
__device__ __half g_yn_h[(size_t)MTOK*DIN];

// ---------------- helpers ----------------
__device__ __forceinline__ uint32_t smem_u32(const void* p) {
    uint32_t a;
    asm("{ .reg .u64 t; cvta.to.shared.u64 t, %1; cvt.u32.u64 %0, t; }" : "=r"(a) : "l"(p));
    return a;
}
__device__ __forceinline__ void cp_async16(uint32_t dst, const void* src, int srcsize) {
    asm volatile("cp.async.ca.shared.global [%0], [%1], 16, %2;"
                 :: "r"(dst), "l"(src), "r"(srcsize) : "memory");
}
#define CP_COMMIT() asm volatile("cp.async.commit_group;" ::: "memory")
#define CP_WAIT0()  asm volatile("cp.async.wait_group 0;" ::: "memory")
#define CP_WAIT1()  asm volatile("cp.async.wait_group 1;" ::: "memory")

__device__ __forceinline__ void ldmx4(uint32_t* r, uint32_t addr) {
    asm volatile("ldmatrix.sync.aligned.m8n8.x4.shared.b16 {%0,%1,%2,%3}, [%4];"
                 : "=r"(r[0]), "=r"(r[1]), "=r"(r[2]), "=r"(r[3]) : "r"(addr));
}
__device__ __forceinline__ void mma16816h(float* d, const uint32_t* a, const uint32_t* b) {
    asm volatile(
        "mma.sync.aligned.m16n8k16.row.col.f32.f16.f16.f32 "
        "{%0,%1,%2,%3}, {%4,%5,%6,%7}, {%8,%9}, {%0,%1,%2,%3};"
        : "+f"(d[0]), "+f"(d[1]), "+f"(d[2]), "+f"(d[3])
        : "r"(a[0]), "r"(a[1]), "r"(a[2]), "r"(a[3]), "r"(b[0]), "r"(b[1]));
}

// ---------------- fp32 -> fp16 convert (single plane) ----------------
__global__ void convert_kernel(const float* __restrict__ src, int dst_sel, size_t n4)
{
    size_t i = (size_t)blockIdx.x*256 + threadIdx.x;
    if (i >= n4) return;
    __half* dst = (dst_sel == 0) ? g_hs_h : (dst_sel == 1) ? g_w1_h : g_w2_h;
    float4 v = reinterpret_cast<const float4*>(src)[i];
    reinterpret_cast<__half2*>(dst)[i*2]   = __halves2half2(
        __float2half_rn(v.x), __float2half_rn(v.y));
    reinterpret_cast<__half2*>(dst)[i*2+1] = __halves2half2(
        __float2half_rn(v.z), __float2half_rn(v.w));
}

// ============ tensor-core GEMM: C[M,N] = A[M,K]*B[N,K]^T, fp16 single-pass ============
// R13 skeleton verbatim: CTA 128x128, BK=32, 2 buffers, 2 barriers per chunk,
// 80B padded rows, affine addressing. Planes: A, B (single each).
#define BK      32
#define SAK_B   80
#define PLANE_B (128*SAK_B)             /* 10240 B per plane        */
#define BUF_B   (2*PLANE_B)             /* A + B = 20480 B          */
#define SMT     (2*BUF_B)               /* 40960 B total            */

__global__ void __launch_bounds__(256) gemm_mma(int which, float* Cout, int M, int N, int Kd)
{
    extern __shared__ char sm[];
    const __half *Ap, *Bp;
    float* Cp;
    if (which == 0) { Ap=g_hs_h; Bp=g_w1_h; Cp=g_zx; }
    else            { Ap=g_yn_h; Bp=g_w2_h; Cp=Cout; }

    const uint32_t sb = smem_u32(sm);
    const int tid  = threadIdx.x;
    const int lane = tid & 31, wid = tid >> 5;
    const int wm = wid & 1, wn = wid >> 1;          // 2 x 4 warp grid
    const int lr = lane >> 2, lc = lane & 3;
    const int m0 = blockIdx.y * 128, n0 = blockIdx.x * 128;
    const int nk = Kd / BK;

    // staging: 4 cp.async per thread (A: 2 iters, B: 2 iters)
    auto stage = [&](int kc, int buf) {
        const int k0 = kc * BK;
        const uint32_t base = sb + buf * BUF_B;
#pragma unroll
        for (int it = 0; it < 2; it++) {
            int idx = it*256 + tid;                  // 0..511
            int row = idx >> 2, ch = idx & 3;
            const __half* s = Ap + (size_t)(m0 + row)*Kd + k0 + ch*8;
            cp_async16(base + row*SAK_B + ch*16, s, 16);
        }
#pragma unroll
        for (int it = 0; it < 2; it++) {
            int idx = it*256 + tid;
            int row = idx >> 2, ch = idx & 3;
            int gn = n0 + row;
            const __half* s = Bp + (size_t)gn*Kd + k0 + ch*8;
            cp_async16(base + PLANE_B + row*SAK_B + ch*16, s, gn < N ? 16 : 0);
        }
    };

    float d[4][4][4];
#pragma unroll
    for (int mi = 0; mi < 4; mi++)
#pragma unroll
        for (int ni = 0; ni < 4; ni++)
#pragma unroll
            for (int r = 0; r < 4; r++) d[mi][ni][r] = 0.f;

    stage(0, 0); CP_COMMIT();

    for (int k = 0; k < nk; k++) {
        const int buf = k & 1;
        if (k + 1 < nk) { stage(k + 1, buf ^ 1); CP_COMMIT(); CP_WAIT1(); }
        else            { CP_WAIT0(); }
        __syncthreads();

        const uint32_t base = sb + buf * BUF_B;
        const int arow = wm*64 + (lane & 15);
        const int akof = (lane & 16) ? 16 : 0;       // bytes (8 fp16)
        const int bkof = (lane & 8)  ? 16 : 0;
#pragma unroll
        for (int ks = 0; ks < BK; ks += 16) {
            uint32_t ah[4][4], bh[2][4];
#pragma unroll
            for (int mi = 0; mi < 4; mi++) {
                uint32_t ao = (uint32_t)((arow + mi*16)*SAK_B + ks*2 + akof);
                ldmx4(ah[mi], base + ao);
            }
#pragma unroll
            for (int pr = 0; pr < 2; pr++) {
                int brow = wn*32 + pr*16 + (lane & 7) + ((lane & 16) ? 8 : 0);
                uint32_t bo = (uint32_t)(brow*SAK_B + ks*2 + bkof);
                ldmx4(bh[pr], base + PLANE_B + bo);
            }
#pragma unroll
            for (int mi = 0; mi < 4; mi++)
#pragma unroll
                for (int ni = 0; ni < 4; ni++)
                    mma16816h(d[mi][ni], ah[mi], &bh[ni>>1][(ni&1)*2]);
        }
        __syncthreads();
    }

    // epilogue
#pragma unroll
    for (int mi = 0; mi < 4; mi++) {
        int m = m0 + wm*64 + mi*16 + lr;
#pragma unroll
        for (int ni = 0; ni < 4; ni++) {
            int n = n0 + wn*32 + ni*8 + lc*2;
            if (n < N) {
                *reinterpret_cast<float2*>(Cp + (size_t)m*N + n) =
                    make_float2(d[mi][ni][0], d[mi][ni][1]);
                *reinterpret_cast<float2*>(Cp + (size_t)(m+8)*N + n) =
                    make_float2(d[mi][ni][2], d[mi][ni][3]);
            }
        }
    }
}

// ---------------- causal conv1d (K=4) + bias + silu, 32-token smem tile ----------------
#define CMT 32
__global__ void __launch_bounds__(256) conv_kernel(const float* __restrict__ w,
                                                   const float* __restrict__ bias)
{
    __shared__ float s[CMT + 3][256];
    const int tid = threadIdx.x;
    const int m0  = blockIdx.x * CMT;
    const int ch  = blockIdx.y * 256 + tid;

#pragma unroll
    for (int i = 0; i < CMT + 3; i++) {
        int gm = m0 - 3 + i;
        if (gm < 0) gm = 0;
        s[i][tid] = g_zx[(size_t)gm*PROJ + DIN + ch];
    }
    __syncthreads();

    const float w0 = w[ch*KCONV+0], w1 = w[ch*KCONV+1],
                w2 = w[ch*KCONV+2], w3 = w[ch*KCONV+3];
    const float b = bias[ch];
#pragma unroll
    for (int i = 0; i < CMT; i++) {
        int m = m0 + i;
        int t = m & (SEQ-1);
        float acc = b;
        if (t >= 3) acc += s[i  ][tid] * w0;
        if (t >= 2) acc += s[i+1][tid] * w1;
        if (t >= 1) acc += s[i+2][tid] * w2;
        acc += s[i+3][tid] * w3;
        acc = acc / (1.f + expf(-acc));
        g_conv[(size_t)m*CONVD + ch] = acc;
    }
}

// ---------------- dt = softplus(dt_raw + dt_bias) ----------------
__global__ void dt_kernel(const float* __restrict__ dtb)
{
    int id = blockIdx.x*256 + threadIdx.x;          // m*64+h
    int m = id >> 6, h = id & 63;
    float v = g_zx[(size_t)m*PROJ + DIN + CONVD + h] + dtb[h];
    g_dt[id] = (v > 20.f) ? v : log1pf(expf(v));
}

// ---------------- SSD as the exact sequential recurrence (R13 anchor) ----------------
__global__ void __launch_bounds__(512) ssd_kernel(const float* __restrict__ A_log,
                                                  const float* __restrict__ Dv)
{
    const int h = blockIdx.x;
    const int b = blockIdx.y;
    const int tid = threadIdx.x;
    const int p = tid >> 3, q = tid & 7;

    __shared__ float sB[TILE][DSTATE];
    __shared__ float sC[TILE][DSTATE];
    __shared__ float sX[TILE][HDIM];
    __shared__ float s_dt[TILE], s_eadt[TILE];

    const float A  = -expf(A_log[h]);
    const float Dh = Dv[h];

    float H[16];
#pragma unroll
    for (int j = 0; j < 16; j++) H[j] = 0.f;

    for (int t0 = 0; t0 < SEQ; t0 += TILE) {
        const size_t mbase = (size_t)b*SEQ + t0;
#pragma unroll
        for (int it = 0; it < 4; it++) {
            int idx = it*512 + tid;
            int r = idx >> 6, c = idx & 63;
            const float* rowp = g_conv + (mbase + r)*CONVD + DIN;
            if (c < 32) *(float4*)&sB[r][c*4]      = *(const float4*)(rowp + c*4);
            else        *(float4*)&sC[r][(c-32)*4] = *(const float4*)(rowp + DSTATE + (c-32)*4);
        }
        {
            int r = tid >> 4, c = tid & 15;
            *(float4*)&sX[r][c*4] =
                *(const float4*)(g_conv + (mbase + r)*CONVD + h*HDIM + c*4);
        }
        if (tid < TILE) {
            float dtv = g_dt[(mbase + tid)*NHEAD + h];
            s_dt[tid]   = dtv;
            s_eadt[tid] = expf(A * dtv);
        }
        __syncthreads();

        for (int ll = 0; ll < TILE; ll++) {
            float e = s_eadt[ll];
            float f = s_dt[ll] * sX[ll][p];
            float part = 0.f;
#pragma unroll
            for (int j = 0; j < 8; j++) {
                int col = j*16 + q*2;
                float2 bb = *(const float2*)&sB[ll][col];
                float2 cc = *(const float2*)&sC[ll][col];
                H[2*j]   = e*H[2*j]   + f*bb.x;
                H[2*j+1] = e*H[2*j+1] + f*bb.y;
                part += cc.x*H[2*j] + cc.y*H[2*j+1];
            }
            part += __shfl_down_sync(0xffffffffu, part, 4, 8);
            part += __shfl_down_sync(0xffffffffu, part, 2, 8);
            part += __shfl_down_sync(0xffffffffu, part, 1, 8);
            if (q == 0)
                g_y[(mbase + ll)*DIN + h*HDIM + p] = part + Dh * sX[ll][p];
        }
        __syncthreads();
    }
}

// ---------------- gated RMSNorm -> single fp16 plane ----------------
__global__ void __launch_bounds__(256) rmsnorm_kernel(const float* __restrict__ w)
{
    int m = blockIdx.x;
    int tid = threadIdx.x;
    float prod[16];
    float ss = 0.f;
#pragma unroll
    for (int i = 0; i < 16; i++) {
        int col = i*256 + tid;
        float y = g_y[(size_t)m*DIN + col];
        float z = g_zx[(size_t)m*PROJ + col];
        float p = y * (z / (1.f + expf(-z)));
        prod[i] = p;
        ss += p*p;
    }
    __shared__ float red[256];
    red[tid] = ss;
    __syncthreads();
    for (int off = 128; off; off >>= 1) {
        if (tid < off) red[tid] += red[tid + off];
        __syncthreads();
    }
    float scale = rsqrtf(red[0] / (float)DIN + 1e-5f);
#pragma unroll
    for (int i = 0; i < 16; i++) {
        int col = i*256 + tid;
        g_yn_h[(size_t)m*DIN + col] = __float2half_rn(prod[i] * scale * w[col]);
    }
}

// ---------------- launch ----------------
extern "C" void kernel_launch(void* const* d_in, const int* in_sizes, int n_in,
                              void* d_out, int out_size)
{
    const float* hs   = (const float*)d_in[0];
    const float* w1   = (const float*)d_in[1];
    const float* cw   = (const float*)d_in[2];
    const float* cb   = (const float*)d_in[3];
    const float* dtb  = (const float*)d_in[4];
    const float* alog = (const float*)d_in[5];
    const float* Dv   = (const float*)d_in[6];
    const float* nw   = (const float*)d_in[7];
    const float* w2   = (const float*)d_in[8];
    float* out = (float*)d_out;

    static int smem_set = 0;
    if (!smem_set) {
        cudaFuncSetAttribute(gemm_mma, cudaFuncAttributeMaxDynamicSharedMemorySize, SMT);
        smem_set = 1;
    }

    // 0. pre-convert GEMM inputs to fp16 planes
    convert_kernel<<<(MTOK*(size_t)HIDV/4 + 255)/256, 256>>>(hs, 0, MTOK*(size_t)HIDV/4);
    convert_kernel<<<(PROJ*(size_t)HIDV/4 + 255)/256, 256>>>(w1, 1, PROJ*(size_t)HIDV/4);
    convert_kernel<<<(HIDV*(size_t)DIN/4 + 255)/256, 256>>>(w2, 2, HIDV*(size_t)DIN/4);

    // 1. in_proj GEMM: g_zx[8192,8512] = hs @ w1^T
    gemm_mma<<<dim3((PROJ+127)/128, MTOK/128), 256, SMT>>>(0, nullptr, MTOK, PROJ, HIDV);
    // 2. conv + silu (tiled)
    conv_kernel<<<dim3(MTOK/CMT, CONVD/256), 256>>>(cw, cb);
    // 3. dt softplus
    dt_kernel<<<(MTOK*NHEAD)/256, 256>>>(dtb);
    // 4. SSD recurrence
    ssd_kernel<<<dim3(NHEAD, BATCH), 512>>>(alog, Dv);
    // 5. gated rmsnorm -> fp16
    rmsnorm_kernel<<<MTOK, 256>>>(nw);
    // 6. out_proj GEMM: out[8192,2048] = yn @ w2^T
    gemm_mma<<<dim3(HIDV/128, MTOK/128), 256, SMT>>>(1, out, MTOK, HIDV, DIN);
}

// round 17
// speedup vs baseline: 1.3047x; 1.0091x over previous
#include <cuda_runtime.h>
#include <cuda_fp16.h>
#include <math.h>
#include <stdint.h>

#define BATCH   2
#define SEQ     4096
#define HIDV    2048
#define DSTATE  128
#define KCONV   4
#define DIN     4096
#define HDIM    64
#define NHEAD   64
#define CONVD   (DIN + 2*DSTATE)        /* 4352 */
#define PROJ    (2*(DIN+DSTATE)+NHEAD)  /* 8512 */
#define MTOK    (BATCH*SEQ)             /* 8192 */
#define TILE    32

// ---------------- scratch (no allocations allowed) ----------------
__device__ float g_zx  [(size_t)MTOK*PROJ];    // in_proj output (fp32)
__device__ float g_conv[(size_t)MTOK*CONVD];   // conv+silu output
__device__ float g_dt  [MTOK*NHEAD];           // softplus(dt+bias)
__device__ float g_y   [(size_t)MTOK*DIN];     // SSD output (pre-norm)

// fp16 planes for tensor-core GEMMs (single plane per operand)
__device__ __half g_hs_h[(size_t)MTOK*HIDV];
__device__ __half g_w1_h[(size_t)PROJ*HIDV];
__device__ __half g_w2_h[(size_t)HIDV*DIN];
__device__ __half g_yn_h[(size_t)MTOK*DIN];

// ---------------- helpers ----------------
__device__ __forceinline__ uint32_t smem_u32(const void* p) {
    uint32_t a;
    asm("{ .reg .u64 t; cvta.to.shared.u64 t, %1; cvt.u32.u64 %0, t; }" : "=r"(a) : "l"(p));
    return a;
}
__device__ __forceinline__ void cp_async16(uint32_t dst, const void* src, int srcsize) {
    asm volatile("cp.async.ca.shared.global [%0], [%1], 16, %2;"
                 :: "r"(dst), "l"(src), "r"(srcsize) : "memory");
}
#define CP_COMMIT() asm volatile("cp.async.commit_group;" ::: "memory")
#define CP_WAIT0()  asm volatile("cp.async.wait_group 0;" ::: "memory")
#define CP_WAIT1()  asm volatile("cp.async.wait_group 1;" ::: "memory")

__device__ __forceinline__ void ldmx4(uint32_t* r, uint32_t addr) {
    asm volatile("ldmatrix.sync.aligned.m8n8.x4.shared.b16 {%0,%1,%2,%3}, [%4];"
                 : "=r"(r[0]), "=r"(r[1]), "=r"(r[2]), "=r"(r[3]) : "r"(addr));
}
__device__ __forceinline__ void mma16816h(float* d, const uint32_t* a, const uint32_t* b) {
    asm volatile(
        "mma.sync.aligned.m16n8k16.row.col.f32.f16.f16.f32 "
        "{%0,%1,%2,%3}, {%4,%5,%6,%7}, {%8,%9}, {%0,%1,%2,%3};"
        : "+f"(d[0]), "+f"(d[1]), "+f"(d[2]), "+f"(d[3])
        : "r"(a[0]), "r"(a[1]), "r"(a[2]), "r"(a[3]), "r"(b[0]), "r"(b[1]));
}

// ---------------- fp32 -> fp16 convert (single plane) ----------------
__global__ void convert_kernel(const float* __restrict__ src, int dst_sel, size_t n4)
{
    size_t i = (size_t)blockIdx.x*256 + threadIdx.x;
    if (i >= n4) return;
    __half* dst = (dst_sel == 0) ? g_hs_h : (dst_sel == 1) ? g_w1_h : g_w2_h;
    float4 v = reinterpret_cast<const float4*>(src)[i];
    reinterpret_cast<__half2*>(dst)[i*2]   = __halves2half2(
        __float2half_rn(v.x), __float2half_rn(v.y));
    reinterpret_cast<__half2*>(dst)[i*2+1] = __halves2half2(
        __float2half_rn(v.z), __float2half_rn(v.w));
}

// ============ tensor-core GEMM: C[M,N] = A[M,K]*B[N,K]^T, fp16 single-pass ============
// 80B-row slab layout (proven). Each pipeline buffer holds TWO consecutive
// 32-K slabs (A+B each), so the barrier/wait tax is paid once per 64 K.
#define BK      32                      /* K per slab                 */
#define KSTEP   64                      /* K per pipeline chunk (2 slabs) */
#define SAK_B   80
#define PLANE_B (128*SAK_B)             /* 10240 B per plane          */
#define SLAB_B  (2*PLANE_B)             /* A + B planes = 20480 B     */
#define BUF_B   (2*SLAB_B)              /* two slabs = 40960 B        */
#define SMT     (2*BUF_B)               /* 81920 B -> 2 CTAs/SM       */

__global__ void __launch_bounds__(256) gemm_mma(int which, float* Cout, int M, int N, int Kd)
{
    extern __shared__ char sm[];
    const __half *Ap, *Bp;
    float* Cp;
    if (which == 0) { Ap=g_hs_h; Bp=g_w1_h; Cp=g_zx; }
    else            { Ap=g_yn_h; Bp=g_w2_h; Cp=Cout; }

    const uint32_t sb = smem_u32(sm);
    const int tid  = threadIdx.x;
    const int lane = tid & 31, wid = tid >> 5;
    const int wm = wid & 1, wn = wid >> 1;          // 2 x 4 warp grid
    const int lr = lane >> 2, lc = lane & 3;
    const int m0 = blockIdx.y * 128, n0 = blockIdx.x * 128;
    const int nk = Kd / KSTEP;

    // stage one 64-K chunk (two slabs): 8 cp.async per thread
    auto stage = [&](int kc, int buf) {
        const uint32_t base = sb + buf * BUF_B;
#pragma unroll
        for (int s = 0; s < 2; s++) {
            const int k0 = kc * KSTEP + s * BK;
            const uint32_t sbase = base + s * SLAB_B;
#pragma unroll
            for (int it = 0; it < 2; it++) {
                int idx = it*256 + tid;              // 0..511
                int row = idx >> 2, ch = idx & 3;
                const __half* src = Ap + (size_t)(m0 + row)*Kd + k0 + ch*8;
                cp_async16(sbase + row*SAK_B + ch*16, src, 16);
            }
#pragma unroll
            for (int it = 0; it < 2; it++) {
                int idx = it*256 + tid;
                int row = idx >> 2, ch = idx & 3;
                int gn = n0 + row;
                const __half* src = Bp + (size_t)gn*Kd + k0 + ch*8;
                cp_async16(sbase + PLANE_B + row*SAK_B + ch*16, src, gn < N ? 16 : 0);
            }
        }
    };

    float d[4][4][4];
#pragma unroll
    for (int mi = 0; mi < 4; mi++)
#pragma unroll
        for (int ni = 0; ni < 4; ni++)
#pragma unroll
            for (int r = 0; r < 4; r++) d[mi][ni][r] = 0.f;

    stage(0, 0); CP_COMMIT();

    for (int k = 0; k < nk; k++) {
        const int buf = k & 1;
        if (k + 1 < nk) { stage(k + 1, buf ^ 1); CP_COMMIT(); CP_WAIT1(); }
        else            { CP_WAIT0(); }
        __syncthreads();

        const int arow = wm*64 + (lane & 15);
        const int akof = (lane & 16) ? 16 : 0;       // bytes (8 fp16)
        const int bkof = (lane & 8)  ? 16 : 0;
        const int browl = (lane & 7) + ((lane & 16) ? 8 : 0);
#pragma unroll
        for (int s = 0; s < 2; s++) {
            const uint32_t base = sb + buf * BUF_B + s * SLAB_B;
#pragma unroll
            for (int ks = 0; ks < BK; ks += 16) {
                uint32_t ah[4][4], bh[2][4];
#pragma unroll
                for (int mi = 0; mi < 4; mi++) {
                    uint32_t ao = (uint32_t)((arow + mi*16)*SAK_B + ks*2 + akof);
                    ldmx4(ah[mi], base + ao);
                }
#pragma unroll
                for (int pr = 0; pr < 2; pr++) {
                    int brow = wn*32 + pr*16 + browl;
                    uint32_t bo = (uint32_t)(brow*SAK_B + ks*2 + bkof);
                    ldmx4(bh[pr], base + PLANE_B + bo);
                }
#pragma unroll
                for (int mi = 0; mi < 4; mi++)
#pragma unroll
                    for (int ni = 0; ni < 4; ni++)
                        mma16816h(d[mi][ni], ah[mi], &bh[ni>>1][(ni&1)*2]);
            }
        }
        __syncthreads();
    }

    // epilogue
#pragma unroll
    for (int mi = 0; mi < 4; mi++) {
        int m = m0 + wm*64 + mi*16 + lr;
#pragma unroll
        for (int ni = 0; ni < 4; ni++) {
            int n = n0 + wn*32 + ni*8 + lc*2;
            if (n < N) {
                *reinterpret_cast<float2*>(Cp + (size_t)m*N + n) =
                    make_float2(d[mi][ni][0], d[mi][ni][1]);
                *reinterpret_cast<float2*>(Cp + (size_t)(m+8)*N + n) =
                    make_float2(d[mi][ni][2], d[mi][ni][3]);
            }
        }
    }
}

// ---------------- causal conv1d (K=4) + bias + silu, 32-token smem tile ----------------
#define CMT 32
__global__ void __launch_bounds__(256) conv_kernel(const float* __restrict__ w,
                                                   const float* __restrict__ bias)
{
    __shared__ float s[CMT + 3][256];
    const int tid = threadIdx.x;
    const int m0  = blockIdx.x * CMT;
    const int ch  = blockIdx.y * 256 + tid;

#pragma unroll
    for (int i = 0; i < CMT + 3; i++) {
        int gm = m0 - 3 + i;
        if (gm < 0) gm = 0;
        s[i][tid] = g_zx[(size_t)gm*PROJ + DIN + ch];
    }
    __syncthreads();

    const float w0 = w[ch*KCONV+0], w1 = w[ch*KCONV+1],
                w2 = w[ch*KCONV+2], w3 = w[ch*KCONV+3];
    const float b = bias[ch];
#pragma unroll
    for (int i = 0; i < CMT; i++) {
        int m = m0 + i;
        int t = m & (SEQ-1);
        float acc = b;
        if (t >= 3) acc += s[i  ][tid] * w0;
        if (t >= 2) acc += s[i+1][tid] * w1;
        if (t >= 1) acc += s[i+2][tid] * w2;
        acc += s[i+3][tid] * w3;
        acc = acc / (1.f + expf(-acc));
        g_conv[(size_t)m*CONVD + ch] = acc;
    }
}

// ---------------- dt = softplus(dt_raw + dt_bias) ----------------
__global__ void dt_kernel(const float* __restrict__ dtb)
{
    int id = blockIdx.x*256 + threadIdx.x;          // m*64+h
    int m = id >> 6, h = id & 63;
    float v = g_zx[(size_t)m*PROJ + DIN + CONVD + h] + dtb[h];
    g_dt[id] = (v > 20.f) ? v : log1pf(expf(v));
}

// ---------------- SSD recurrence: R13 grid/layout, float4 inner loads ----------------
// grid (NHEAD, BATCH), 512 threads. p = tid>>3 (0..63), q = tid&7.
// Thread owns n = j*32 + q*4 + {0..3}, j=0..3 (16 H values, float4 groups).
// LDS.128: lanes read 8 distinct 16B chunks spanning 128B, 4-way broadcast
// across p -> conflict-free. 8 LDS per token vs 16 in R13.
__global__ void __launch_bounds__(512) ssd_kernel(const float* __restrict__ A_log,
                                                  const float* __restrict__ Dv)
{
    const int h = blockIdx.x;
    const int b = blockIdx.y;
    const int tid = threadIdx.x;
    const int p = tid >> 3, q = tid & 7;

    __shared__ float sB[TILE][DSTATE];
    __shared__ float sC[TILE][DSTATE];
    __shared__ float sX[TILE][HDIM];
    __shared__ float s_dt[TILE], s_eadt[TILE];

    const float A  = -expf(A_log[h]);
    const float Dh = Dv[h];

    float H[16];
#pragma unroll
    for (int j = 0; j < 16; j++) H[j] = 0.f;

    for (int t0 = 0; t0 < SEQ; t0 += TILE) {
        const size_t mbase = (size_t)b*SEQ + t0;
#pragma unroll
        for (int it = 0; it < 4; it++) {
            int idx = it*512 + tid;
            int r = idx >> 6, c = idx & 63;
            const float* rowp = g_conv + (mbase + r)*CONVD + DIN;
            if (c < 32) *(float4*)&sB[r][c*4]      = *(const float4*)(rowp + c*4);
            else        *(float4*)&sC[r][(c-32)*4] = *(const float4*)(rowp + DSTATE + (c-32)*4);
        }
        {
            int r = tid >> 4, c = tid & 15;
            *(float4*)&sX[r][c*4] =
                *(const float4*)(g_conv + (mbase + r)*CONVD + h*HDIM + c*4);
        }
        if (tid < TILE) {
            float dtv = g_dt[(mbase + tid)*NHEAD + h];
            s_dt[tid]   = dtv;
            s_eadt[tid] = expf(A * dtv);
        }
        __syncthreads();

        for (int ll = 0; ll < TILE; ll++) {
            float e = s_eadt[ll];
            float f = s_dt[ll] * sX[ll][p];
            float part = 0.f;
#pragma unroll
            for (int j = 0; j < 4; j++) {
                int col = j*32 + q*4;
                float4 bb = *(const float4*)&sB[ll][col];
                float4 cc = *(const float4*)&sC[ll][col];
                H[4*j+0] = e*H[4*j+0] + f*bb.x;
                H[4*j+1] = e*H[4*j+1] + f*bb.y;
                H[4*j+2] = e*H[4*j+2] + f*bb.z;
                H[4*j+3] = e*H[4*j+3] + f*bb.w;
                part += cc.x*H[4*j+0] + cc.y*H[4*j+1]
                      + cc.z*H[4*j+2] + cc.w*H[4*j+3];
            }
            part += __shfl_down_sync(0xffffffffu, part, 4, 8);
            part += __shfl_down_sync(0xffffffffu, part, 2, 8);
            part += __shfl_down_sync(0xffffffffu, part, 1, 8);
            if (q == 0)
                g_y[(mbase + ll)*DIN + h*HDIM + p] = part + Dh * sX[ll][p];
        }
        __syncthreads();
    }
}

// ---------------- gated RMSNorm -> single fp16 plane ----------------
__global__ void __launch_bounds__(256) rmsnorm_kernel(const float* __restrict__ w)
{
    int m = blockIdx.x;
    int tid = threadIdx.x;
    float prod[16];
    float ss = 0.f;
#pragma unroll
    for (int i = 0; i < 16; i++) {
        int col = i*256 + tid;
        float y = g_y[(size_t)m*DIN + col];
        float z = g_zx[(size_t)m*PROJ + col];
        float p = y * (z / (1.f + expf(-z)));
        prod[i] = p;
        ss += p*p;
    }
    __shared__ float red[256];
    red[tid] = ss;
    __syncthreads();
    for (int off = 128; off; off >>= 1) {
        if (tid < off) red[tid] += red[tid + off];
        __syncthreads();
    }
    float scale = rsqrtf(red[0] / (float)DIN + 1e-5f);
#pragma unroll
    for (int i = 0; i < 16; i++) {
        int col = i*256 + tid;
        g_yn_h[(size_t)m*DIN + col] = __float2half_rn(prod[i] * scale * w[col]);
    }
}

// ---------------- launch ----------------
extern "C" void kernel_launch(void* const* d_in, const int* in_sizes, int n_in,
                              void* d_out, int out_size)
{
    const float* hs   = (const float*)d_in[0];
    const float* w1   = (const float*)d_in[1];
    const float* cw   = (const float*)d_in[2];
    const float* cb   = (const float*)d_in[3];
    const float* dtb  = (const float*)d_in[4];
    const float* alog = (const float*)d_in[5];
    const float* Dv   = (const float*)d_in[6];
    const float* nw   = (const float*)d_in[7];
    const float* w2   = (const float*)d_in[8];
    float* out = (float*)d_out;

    static int smem_set = 0;
    if (!smem_set) {
        cudaFuncSetAttribute(gemm_mma, cudaFuncAttributeMaxDynamicSharedMemorySize, SMT);
        smem_set = 1;
    }

    // 0. pre-convert GEMM inputs to fp16 planes
    convert_kernel<<<(MTOK*(size_t)HIDV/4 + 255)/256, 256>>>(hs, 0, MTOK*(size_t)HIDV/4);
    convert_kernel<<<(PROJ*(size_t)HIDV/4 + 255)/256, 256>>>(w1, 1, PROJ*(size_t)HIDV/4);
    convert_kernel<<<(HIDV*(size_t)DIN/4 + 255)/256, 256>>>(w2, 2, HIDV*(size_t)DIN/4);

    // 1. in_proj GEMM: g_zx[8192,8512] = hs @ w1^T
    gemm_mma<<<dim3((PROJ+127)/128, MTOK/128), 256, SMT>>>(0, nullptr, MTOK, PROJ, HIDV);
    // 2. conv + silu (tiled)
    conv_kernel<<<dim3(MTOK/CMT, CONVD/256), 256>>>(cw, cb);
    // 3. dt softplus
    dt_kernel<<<(MTOK*NHEAD)/256, 256>>>(dtb);
    // 4. SSD recurrence (float4 loads, R13 grid)
    ssd_kernel<<<dim3(NHEAD, BATCH), 512>>>(alog, Dv);
    // 5. gated rmsnorm -> fp16
    rmsnorm_kernel<<<MTOK, 256>>>(nw);
    // 6. out_proj GEMM: out[8192,2048] = yn @ w2^T
    gemm_mma<<<dim3(HIDV/128, MTOK/128), 256, SMT>>>(1, out, MTOK, HIDV, DIN);
}